// round 3
// baseline (speedup 1.0000x reference)
#include <cuda_runtime.h>

// Problem constants
#define TT   256
#define BB   64
#define II   512
#define HH   1024
#define G4H  4096
#define SBUF (3 * BB * HH)   // one full [L,B,H] state buffer

// Ping-pong state buffers (device globals: no allocation allowed)
__device__ float g_h[2 * SBUF];
__device__ float g_c[2 * SBUF];
__device__ int   g_len[BB];

__device__ __forceinline__ float sigf(float x) {
    return 1.0f / (1.0f + __expf(-x));
}

// Normalize length input to int32, robust to int32-vs-int64 storage.
// Reads only the first 256 bytes for detection (in-bounds either way).
__global__ void prep_len_kernel(const void* lenbuf) {
    if (threadIdx.x == 0 && blockIdx.x == 0) {
        const long long* L64 = (const long long*)lenbuf;
        const int*       L32 = (const int*)lenbuf;
        bool is64 = true;
        for (int b = 0; b < 32; b++) {           // 256 bytes: safe both ways
            long long v = L64[b];
            if (v < 0 || v > TT) { is64 = false; break; }
        }
        for (int b = 0; b < BB; b++) {
            g_len[b] = is64 ? (int)L64[b] : L32[b];
        }
    }
}

__global__ void init_state_kernel(const float* __restrict__ h0,
                                  const float* __restrict__ c0) {
    int i = blockIdx.x * blockDim.x + threadIdx.x;
    if (i < SBUF) {
        g_h[i] = h0[i];   // buffer 0 holds the t=0 "previous" state
        g_c[i] = c0[i];
    }
}

__global__ void finalize_kernel(float* __restrict__ Hout,
                                float* __restrict__ Cout) {
    // After t=255 (odd), the current state lives in buffer 0.
    int i = blockIdx.x * blockDim.x + threadIdx.x;
    if (i < SBUF) {
        Hout[i] = g_h[i];
        Cout[i] = g_c[i];
    }
}

// Generic fused LSTM layer:
//   z[b][j] = bias[j] + sum_s In_s[b,:] @ W_s[:,j]   (j = g*H + n, gate order f,i,o,g)
//   c1 = sig(f)*c_old + sig(i)*tanh(g) ; h1 = sig(o)*tanh(c1)
//   masked update: keep old state where t >= length[b]
// CTA tile: 16 b  x  32 n  x  4 gates.  Grid = 4 b-tiles * 32 n-tiles = 128 CTAs.
// 128 threads: lane = n_local (0..31), wq = warp id (0..3) -> 4 consecutive b per thread.
__global__ void __launch_bounds__(128, 1)
lstm_layer_kernel(
    const float* __restrict__ in0, const float* __restrict__ W0, int K0,
    const float* __restrict__ in1, const float* __restrict__ W1, int K1,
    const float* __restrict__ in2, const float* __restrict__ W2, int K2,
    const float* __restrict__ bias,
    const float* __restrict__ hprev, const float* __restrict__ cprev,
    float* __restrict__ hout, float* __restrict__ cout,
    float* __restrict__ outp, int t)
{
    __shared__ __align__(16) float a_s[32][18];    // [kk][b_local], padded
    __shared__ __align__(16) float w_s[32][132];   // [kk][n_local*4 + gate], padded

    const int tid  = threadIdx.x;
    const int lane = tid & 31;          // n_local
    const int wq   = tid >> 5;          // 0..3, b-quad
    const int b0   = (blockIdx.x >> 5) * 16;
    const int n0   = (blockIdx.x & 31) * 32;

    float acc[4][4];
#pragma unroll
    for (int j = 0; j < 4; j++)
#pragma unroll
        for (int g = 0; g < 4; g++) acc[j][g] = 0.0f;

    const float* ins[3] = {in0, in1, in2};
    const float* Ws[3]  = {W0,  W1,  W2};
    const int    Ks[3]  = {K0,  K1,  K2};

#pragma unroll
    for (int s = 0; s < 3; s++) {
        const int K = Ks[s];
        if (K == 0) continue;
        const float* __restrict__ In = ins[s];
        const float* __restrict__ W  = Ws[s];

        for (int kb = 0; kb < K; kb += 32) {
            // Stage activations transposed: a_s[kk][b_off] = In[(b0+b_off)*K + kb+kk]
#pragma unroll
            for (int r = 0; r < 4; r++) {
                const int b_off = wq + 4 * r;
                a_s[lane][b_off] = In[(b0 + b_off) * K + kb + lane];
            }
            // Stage weights gate-interleaved: w_s[kk][nl*4+g] = W[(kb+kk)*4096 + g*1024 + n0+nl]
#pragma unroll
            for (int r = 0; r < 32; r++) {
                const int mm = wq + 4 * r;          // 0..127
                const int kk = mm >> 2;
                const int g  = mm & 3;
                w_s[kk][lane * 4 + g] = W[(kb + kk) * G4H + g * HH + n0 + lane];
            }
            __syncthreads();

#pragma unroll
            for (int kk = 0; kk < 32; kk++) {
                const float4 w4  = *(const float4*)&w_s[kk][lane * 4];       // conflict-free LDS.128
                const float2 a01 = *(const float2*)&a_s[kk][wq * 4];         // uniform -> broadcast
                const float2 a23 = *(const float2*)&a_s[kk][wq * 4 + 2];

                acc[0][0] += a01.x * w4.x; acc[0][1] += a01.x * w4.y;
                acc[0][2] += a01.x * w4.z; acc[0][3] += a01.x * w4.w;

                acc[1][0] += a01.y * w4.x; acc[1][1] += a01.y * w4.y;
                acc[1][2] += a01.y * w4.z; acc[1][3] += a01.y * w4.w;

                acc[2][0] += a23.x * w4.x; acc[2][1] += a23.x * w4.y;
                acc[2][2] += a23.x * w4.z; acc[2][3] += a23.x * w4.w;

                acc[3][0] += a23.y * w4.x; acc[3][1] += a23.y * w4.y;
                acc[3][2] += a23.y * w4.z; acc[3][3] += a23.y * w4.w;
            }
            __syncthreads();
        }
    }

    // Epilogue: bias + gates + masked state update
    const int n  = n0 + lane;
    const float bf = bias[n];
    const float bi = bias[HH + n];
    const float bo = bias[2 * HH + n];
    const float bg = bias[3 * HH + n];

#pragma unroll
    for (int j = 0; j < 4; j++) {
        const int b    = b0 + wq * 4 + j;
        const int sidx = b * HH + n;
        const bool act = (t < g_len[b]);

        const float cold = cprev[sidx];
        const float hold = hprev[sidx];

        const float f  = sigf(acc[j][0] + bf);
        const float ig = sigf(acc[j][1] + bi);
        const float o  = sigf(acc[j][2] + bo);
        const float gg = tanhf(acc[j][3] + bg);

        float c1 = f * cold + ig * gg;
        float h1 = o * tanhf(c1);
        if (!act) { c1 = cold; h1 = hold; }

        cout[sidx] = c1;
        hout[sidx] = h1;
        if (outp) outp[sidx] = h1;   // output[t][b][n] == updated Ht[2]
    }
}

extern "C" void kernel_launch(void* const* d_in, const int* in_sizes, int n_in,
                              void* d_out, int out_size) {
    const float* x    = (const float*)d_in[0];
    const void*  len  = d_in[1];
    const float* h0   = (const float*)d_in[2];
    const float* c0   = (const float*)d_in[3];
    const float* Wbh0 = (const float*)d_in[4];
    const float* Whh0 = (const float*)d_in[5];
    const float* Wth0 = (const float*)d_in[6];
    const float* b0   = (const float*)d_in[7];
    const float* Wbh1 = (const float*)d_in[8];
    const float* Whh1 = (const float*)d_in[9];
    const float* Wth1 = (const float*)d_in[10];
    const float* b1   = (const float*)d_in[11];
    const float* Wih2 = (const float*)d_in[12];
    const float* Whh2 = (const float*)d_in[13];
    const float* b2   = (const float*)d_in[14];

    float* out  = (float*)d_out;                       // [T,B,H]
    float* Hout = out + (size_t)TT * BB * HH;          // [L,B,H]
    float* Cout = Hout + SBUF;                         // [L,B,H]

    void* p;
    cudaGetSymbolAddress(&p, g_h); float* Hs = (float*)p;
    cudaGetSymbolAddress(&p, g_c); float* Cs = (float*)p;

    prep_len_kernel<<<1, 32>>>(len);
    init_state_kernel<<<(SBUF + 255) / 256, 256>>>(h0, c0);

    for (int t = 0; t < TT; t++) {
        const int pv = t & 1;        // t even: prev=buf0, cur=buf1 ; t odd: swapped
        const int cu = pv ^ 1;
        float* hp = Hs + pv * SBUF;
        float* hc = Hs + cu * SBUF;
        float* cp = Cs + pv * SBUF;
        float* cc = Cs + cu * SBUF;

        // layer 0: z = Ht0_prev@Whh0 + x_t@Wbh0 + Ht1_prev@Wth0 + b0
        lstm_layer_kernel<<<128, 128>>>(
            hp + 0 * BB * HH, Whh0, HH,
            x + (size_t)t * BB * II, Wbh0, II,
            hp + 1 * BB * HH, Wth0, HH,
            b0,
            hp + 0 * BB * HH, cp + 0 * BB * HH,
            hc + 0 * BB * HH, cc + 0 * BB * HH,
            nullptr, t);

        // layer 1: z = Ht1_prev@Whh1 + Ht0_new@Wbh1 + Ht2_prev@Wth1 + b1
        lstm_layer_kernel<<<128, 128>>>(
            hp + 1 * BB * HH, Whh1, HH,
            hc + 0 * BB * HH, Wbh1, HH,
            hp + 2 * BB * HH, Wth1, HH,
            b1,
            hp + 1 * BB * HH, cp + 1 * BB * HH,
            hc + 1 * BB * HH, cc + 1 * BB * HH,
            nullptr, t);

        // layer 2: z = Ht2_prev@Whh2 + Ht1_new@Wih2 + b2 ; writes output[t]
        lstm_layer_kernel<<<128, 128>>>(
            hp + 2 * BB * HH, Whh2, HH,
            hc + 1 * BB * HH, Wih2, HH,
            nullptr, nullptr, 0,
            b2,
            hp + 2 * BB * HH, cp + 2 * BB * HH,
            hc + 2 * BB * HH, cc + 2 * BB * HH,
            out + (size_t)t * BB * HH, t);
    }

    finalize_kernel<<<(SBUF + 255) / 256, 256>>>(Hout, Cout);
}

// round 4
// speedup vs baseline: 1.0015x; 1.0015x over previous
#include <cuda_runtime.h>

// Problem constants
#define TT   256
#define BB   64
#define II   512
#define HH   1024
#define G4H  4096
#define SBUF (3 * BB * HH)   // one full [L,B,H] state buffer

// Ping-pong state buffers (device globals: no allocation allowed)
__device__ float g_h[2 * SBUF];
__device__ float g_c[2 * SBUF];
__device__ int   g_len[BB];

__device__ __forceinline__ float sigf(float x) {
    return 1.0f / (1.0f + __expf(-x));
}

// Normalize length input to int32, robust to int32-vs-int64 storage.
// Reads only the first 256 bytes for detection (in-bounds either way).
__global__ void prep_len_kernel(const void* lenbuf) {
    if (threadIdx.x == 0 && blockIdx.x == 0) {
        const long long* L64 = (const long long*)lenbuf;
        const int*       L32 = (const int*)lenbuf;
        bool is64 = true;
        for (int b = 0; b < 32; b++) {           // 256 bytes: safe both ways
            long long v = L64[b];
            if (v < 0 || v > TT) { is64 = false; break; }
        }
        for (int b = 0; b < BB; b++) {
            g_len[b] = is64 ? (int)L64[b] : L32[b];
        }
    }
}

__global__ void init_state_kernel(const float* __restrict__ h0,
                                  const float* __restrict__ c0) {
    int i = blockIdx.x * blockDim.x + threadIdx.x;
    if (i < SBUF) {
        g_h[i] = h0[i];   // buffer 0 holds the t=0 "previous" state
        g_c[i] = c0[i];
    }
}

__global__ void finalize_kernel(float* __restrict__ Hout,
                                float* __restrict__ Cout) {
    // After t=255 (odd), the current state lives in buffer 0.
    int i = blockIdx.x * blockDim.x + threadIdx.x;
    if (i < SBUF) {
        Hout[i] = g_h[i];
        Cout[i] = g_c[i];
    }
}

// Generic fused LSTM layer:
//   z[b][j] = bias[j] + sum_s In_s[b,:] @ W_s[:,j]   (j = g*H + n, gate order f,i,o,g)
//   c1 = sig(f)*c_old + sig(i)*tanh(g) ; h1 = sig(o)*tanh(c1)
//   masked update: keep old state where t >= length[b]
// CTA tile: 16 b  x  32 n  x  4 gates.  Grid = 4 b-tiles * 32 n-tiles = 128 CTAs.
// 128 threads: lane = n_local (0..31), wq = warp id (0..3) -> 4 consecutive b per thread.
__global__ void __launch_bounds__(128, 1)
lstm_layer_kernel(
    const float* __restrict__ in0, const float* __restrict__ W0, int K0,
    const float* __restrict__ in1, const float* __restrict__ W1, int K1,
    const float* __restrict__ in2, const float* __restrict__ W2, int K2,
    const float* __restrict__ bias,
    const float* __restrict__ hprev, const float* __restrict__ cprev,
    float* __restrict__ hout, float* __restrict__ cout,
    float* __restrict__ outp, int t)
{
    __shared__ __align__(16) float a_s[32][18];    // [kk][b_local], padded
    __shared__ __align__(16) float w_s[32][132];   // [kk][n_local*4 + gate], padded

    const int tid  = threadIdx.x;
    const int lane = tid & 31;          // n_local
    const int wq   = tid >> 5;          // 0..3, b-quad
    const int b0   = (blockIdx.x >> 5) * 16;
    const int n0   = (blockIdx.x & 31) * 32;

    float acc[4][4];
#pragma unroll
    for (int j = 0; j < 4; j++)
#pragma unroll
        for (int g = 0; g < 4; g++) acc[j][g] = 0.0f;

    const float* ins[3] = {in0, in1, in2};
    const float* Ws[3]  = {W0,  W1,  W2};
    const int    Ks[3]  = {K0,  K1,  K2};

#pragma unroll
    for (int s = 0; s < 3; s++) {
        const int K = Ks[s];
        if (K == 0) continue;
        const float* __restrict__ In = ins[s];
        const float* __restrict__ W  = Ws[s];

        for (int kb = 0; kb < K; kb += 32) {
            // Stage activations transposed: a_s[kk][b_off] = In[(b0+b_off)*K + kb+kk]
#pragma unroll
            for (int r = 0; r < 4; r++) {
                const int b_off = wq + 4 * r;
                a_s[lane][b_off] = In[(b0 + b_off) * K + kb + lane];
            }
            // Stage weights gate-interleaved: w_s[kk][nl*4+g] = W[(kb+kk)*4096 + g*1024 + n0+nl]
#pragma unroll
            for (int r = 0; r < 32; r++) {
                const int mm = wq + 4 * r;          // 0..127
                const int kk = mm >> 2;
                const int g  = mm & 3;
                w_s[kk][lane * 4 + g] = W[(kb + kk) * G4H + g * HH + n0 + lane];
            }
            __syncthreads();

#pragma unroll
            for (int kk = 0; kk < 32; kk++) {
                const float4 w4  = *(const float4*)&w_s[kk][lane * 4];       // conflict-free LDS.128
                const float2 a01 = *(const float2*)&a_s[kk][wq * 4];         // uniform -> broadcast
                const float2 a23 = *(const float2*)&a_s[kk][wq * 4 + 2];

                acc[0][0] += a01.x * w4.x; acc[0][1] += a01.x * w4.y;
                acc[0][2] += a01.x * w4.z; acc[0][3] += a01.x * w4.w;

                acc[1][0] += a01.y * w4.x; acc[1][1] += a01.y * w4.y;
                acc[1][2] += a01.y * w4.z; acc[1][3] += a01.y * w4.w;

                acc[2][0] += a23.x * w4.x; acc[2][1] += a23.x * w4.y;
                acc[2][2] += a23.x * w4.z; acc[2][3] += a23.x * w4.w;

                acc[3][0] += a23.y * w4.x; acc[3][1] += a23.y * w4.y;
                acc[3][2] += a23.y * w4.z; acc[3][3] += a23.y * w4.w;
            }
            __syncthreads();
        }
    }

    // Epilogue: bias + gates + masked state update
    const int n  = n0 + lane;
    const float bf = bias[n];
    const float bi = bias[HH + n];
    const float bo = bias[2 * HH + n];
    const float bg = bias[3 * HH + n];

#pragma unroll
    for (int j = 0; j < 4; j++) {
        const int b    = b0 + wq * 4 + j;
        const int sidx = b * HH + n;
        const bool act = (t < g_len[b]);

        const float cold = cprev[sidx];
        const float hold = hprev[sidx];

        const float f  = sigf(acc[j][0] + bf);
        const float ig = sigf(acc[j][1] + bi);
        const float o  = sigf(acc[j][2] + bo);
        const float gg = tanhf(acc[j][3] + bg);

        float c1 = f * cold + ig * gg;
        float h1 = o * tanhf(c1);
        if (!act) { c1 = cold; h1 = hold; }

        cout[sidx] = c1;
        hout[sidx] = h1;
        if (outp) outp[sidx] = h1;   // output[t][b][n] == updated Ht[2]
    }
}

extern "C" void kernel_launch(void* const* d_in, const int* in_sizes, int n_in,
                              void* d_out, int out_size) {
    const float* x    = (const float*)d_in[0];
    const void*  len  = d_in[1];
    const float* h0   = (const float*)d_in[2];
    const float* c0   = (const float*)d_in[3];
    const float* Wbh0 = (const float*)d_in[4];
    const float* Whh0 = (const float*)d_in[5];
    const float* Wth0 = (const float*)d_in[6];
    const float* b0   = (const float*)d_in[7];
    const float* Wbh1 = (const float*)d_in[8];
    const float* Whh1 = (const float*)d_in[9];
    const float* Wth1 = (const float*)d_in[10];
    const float* b1   = (const float*)d_in[11];
    const float* Wih2 = (const float*)d_in[12];
    const float* Whh2 = (const float*)d_in[13];
    const float* b2   = (const float*)d_in[14];

    float* out  = (float*)d_out;                       // [T,B,H]
    float* Hout = out + (size_t)TT * BB * HH;          // [L,B,H]
    float* Cout = Hout + SBUF;                         // [L,B,H]

    void* p;
    cudaGetSymbolAddress(&p, g_h); float* Hs = (float*)p;
    cudaGetSymbolAddress(&p, g_c); float* Cs = (float*)p;

    prep_len_kernel<<<1, 32>>>(len);
    init_state_kernel<<<(SBUF + 255) / 256, 256>>>(h0, c0);

    for (int t = 0; t < TT; t++) {
        const int pv = t & 1;        // t even: prev=buf0, cur=buf1 ; t odd: swapped
        const int cu = pv ^ 1;
        float* hp = Hs + pv * SBUF;
        float* hc = Hs + cu * SBUF;
        float* cp = Cs + pv * SBUF;
        float* cc = Cs + cu * SBUF;

        // layer 0: z = Ht0_prev@Whh0 + x_t@Wbh0 + Ht1_prev@Wth0 + b0
        lstm_layer_kernel<<<128, 128>>>(
            hp + 0 * BB * HH, Whh0, HH,
            x + (size_t)t * BB * II, Wbh0, II,
            hp + 1 * BB * HH, Wth0, HH,
            b0,
            hp + 0 * BB * HH, cp + 0 * BB * HH,
            hc + 0 * BB * HH, cc + 0 * BB * HH,
            nullptr, t);

        // layer 1: z = Ht1_prev@Whh1 + Ht0_new@Wbh1 + Ht2_prev@Wth1 + b1
        lstm_layer_kernel<<<128, 128>>>(
            hp + 1 * BB * HH, Whh1, HH,
            hc + 0 * BB * HH, Wbh1, HH,
            hp + 2 * BB * HH, Wth1, HH,
            b1,
            hp + 1 * BB * HH, cp + 1 * BB * HH,
            hc + 1 * BB * HH, cc + 1 * BB * HH,
            nullptr, t);

        // layer 2: z = Ht2_prev@Whh2 + Ht1_new@Wih2 + b2 ; writes output[t]
        lstm_layer_kernel<<<128, 128>>>(
            hp + 2 * BB * HH, Whh2, HH,
            hc + 1 * BB * HH, Wih2, HH,
            nullptr, nullptr, 0,
            b2,
            hp + 2 * BB * HH, cp + 2 * BB * HH,
            hc + 2 * BB * HH, cc + 2 * BB * HH,
            out + (size_t)t * BB * HH, t);
    }

    finalize_kernel<<<(SBUF + 255) / 256, 256>>>(Hout, Cout);
}

// round 6
// speedup vs baseline: 4.4104x; 4.4037x over previous
#include <cuda_runtime.h>
#include <cuda_bf16.h>
#include <cstdint>

#define TT   256
#define BB   64
#define II   512
#define HH   1024
#define SBUF (3 * BB * HH)

#define A_CH 8192      // weight chunk: 32j x 64k x (hi+lo) bf16, fragment order
#define B_CH 16384     // activation chunk: 64b x 64k x (hi+lo) bf16, fragment order
#define NCH0 40        // layer0: h(16) + x(8) + h(16)
#define NCH1 48
#define NCH2 32

#define WIMG_L0 0ULL
#define WIMG_L1 (WIMG_L0 + 128ULL * NCH0 * A_CH)
#define WIMG_L2 (WIMG_L1 + 128ULL * NCH1 * A_CH)
#define WIMG_TOT (WIMG_L2 + 128ULL * NCH2 * A_CH)

__device__ __align__(16) char g_wimg[WIMG_TOT];                    // ~126 MB
__device__ __align__(16) char g_ximg[(size_t)TT * 8 * B_CH];       // 32 MB
__device__ __align__(16) char g_himg[2][3][16 * B_CH];             // 1.5 MB
__device__ float g_h[2 * SBUF];
__device__ float g_c[2 * SBUF];
__device__ int   g_len[BB];

__device__ __forceinline__ uint32_t smem_u32(const void* p) {
    uint32_t a;
    asm("{ .reg .u64 t; cvta.to.shared.u64 t, %1; cvt.u32.u64 %0, t; }" : "=r"(a) : "l"(p));
    return a;
}
__device__ __forceinline__ float sigf(float x) { return 1.0f / (1.0f + __expf(-x)); }
__device__ __forceinline__ uint16_t bf16bits(float v) {
    __nv_bfloat16 b = __float2bfloat16(v);
    return *(uint16_t*)&b;
}
__device__ __forceinline__ float bf16val(uint16_t u) {
    __nv_bfloat16 b = *(__nv_bfloat16*)&u;
    return __bfloat162float(b);
}
// pack two values as bf16x2 (low = first); split=0 -> hi part, split=1 -> residual
__device__ __forceinline__ uint32_t pack_split(float v0, float v1, int split) {
    uint16_t h0 = bf16bits(v0), h1 = bf16bits(v1);
    if (split == 0) return (uint32_t)h0 | ((uint32_t)h1 << 16);
    uint16_t l0 = bf16bits(v0 - bf16val(h0)), l1 = bf16bits(v1 - bf16val(h1));
    return (uint32_t)l0 | ((uint32_t)l1 << 16);
}

#define MMA(c, a, b) \
    asm volatile("mma.sync.aligned.m16n8k16.row.col.f32.bf16.bf16.f32 " \
        "{%0,%1,%2,%3}, {%4,%5,%6,%7}, {%8,%9}, {%0,%1,%2,%3};" \
        : "+f"((c)[0]), "+f"((c)[1]), "+f"((c)[2]), "+f"((c)[3]) \
        : "r"((a).x), "r"((a).y), "r"((a).z), "r"((a).w), "r"((b).x), "r"((b).y))

// ---------------- prep kernels ----------------
__global__ void prep_len_kernel(const void* lenbuf) {
    if (threadIdx.x == 0 && blockIdx.x == 0) {
        const long long* L64 = (const long long*)lenbuf;
        const int*       L32 = (const int*)lenbuf;
        bool is64 = true;
        for (int b = 0; b < 32; b++) {               // first 256 bytes: in-bounds either way
            long long v = L64[b];
            if (v < 0 || v > TT) { is64 = false; break; }
        }
        for (int b = 0; b < BB; b++) g_len[b] = is64 ? (int)L64[b] : L32[b];
    }
}
__global__ void init_state_kernel(const float* __restrict__ h0, const float* __restrict__ c0) {
    int i = blockIdx.x * blockDim.x + threadIdx.x;
    if (i < SBUF) { g_h[i] = h0[i]; g_c[i] = c0[i]; }
}
__global__ void finalize_kernel(float* __restrict__ Hout, float* __restrict__ Cout) {
    int i = blockIdx.x * blockDim.x + threadIdx.x;
    if (i < SBUF) { Hout[i] = g_h[i]; Cout[i] = g_c[i]; }   // t=255 odd -> cur in buf 0
}

// Weight -> A-fragment image. grid=(nq kchunks, 128 jt), 128 thr.
// CTA jt covers j rows {gate*1024 + jt*8 + i : gate 0..3, i 0..7}; jsub0 = gates{0,1}, jsub1 = {2,3}.
__global__ void __launch_bounds__(128) prep_w_kernel(
    const float* __restrict__ W, char* __restrict__ base, int NCH, int so)
{
    __shared__ float sw[64][36];   // [k][jloc: gate*8+i], padded
    const int q = blockIdx.x, jt = blockIdx.y, tid = threadIdx.x;
    const int kb = q * 64;
    char* out = base + ((size_t)jt * NCH + so + q) * A_CH;

#pragma unroll
    for (int r = 0; r < 4; r++) {
        int u = tid + 128 * r;                       // 512 float4 loads
        int k = u >> 3, rem = u & 7, gate = rem >> 1, pair = rem & 1;
        const float4 v = *(const float4*)(W + (size_t)(kb + k) * 4096 + gate * 1024 + jt * 8 + pair * 4);
        float* d = &sw[k][gate * 8 + pair * 4];
        d[0] = v.x; d[1] = v.y; d[2] = v.z; d[3] = v.w;
    }
    __syncthreads();
#pragma unroll
    for (int r = 0; r < 4; r++) {
        int u = tid + 128 * r;                       // 512 x 16B units
        int lane = u & 31, rest = u >> 5;
        int split = rest & 1, jsub = (rest >> 1) & 1, k16 = rest >> 2;
        int g = lane >> 2, tig = lane & 3;
        uint32_t regs[4];
#pragma unroll
        for (int rg = 0; rg < 4; rg++) {             // a0..a3: row g+(rg&1)*8, k 2tig+(rg>>1)*8+{0,1}
            int col = jsub * 16 + (rg & 1) * 8 + g;
            int kx  = k16 * 16 + 2 * tig + (rg >> 1) * 8;
            regs[rg] = pack_split(sw[kx][col], sw[kx + 1][col], split);
        }
        *(uint4*)(out + k16 * 2048 + jsub * 1024 + split * 512 + lane * 16)
            = make_uint4(regs[0], regs[1], regs[2], regs[3]);
    }
}

// Activation -> B-fragment image. grid=(nq kchunks, nouter), 128 thr.
__global__ void __launch_bounds__(128) prep_act_kernel(
    const float* __restrict__ src, int rowlen, char* __restrict__ outbase, int ch_per_outer)
{
    __shared__ float sa[64][68];   // [b][k]
    const int q = blockIdx.x, o = blockIdx.y, tid = threadIdx.x;
    const int kb = q * 64;
    char* out = outbase + ((size_t)o * ch_per_outer + q) * B_CH;

#pragma unroll
    for (int r = 0; r < 8; r++) {
        int u = tid + 128 * r;                       // 1024 float4 loads
        int b = u >> 4, c4 = u & 15;
        const float4 v = *(const float4*)(src + ((size_t)o * BB + b) * rowlen + kb + c4 * 4);
        float* d = &sa[b][c4 * 4];
        d[0] = v.x; d[1] = v.y; d[2] = v.z; d[3] = v.w;
    }
    __syncthreads();
#pragma unroll
    for (int r = 0; r < 16; r++) {
        int u = tid + 128 * r;                       // 2048 x 8B units
        int lane = u & 31, rest = u >> 5;
        int nfrag = rest & 3, split = (rest >> 2) & 1, bgroup = (rest >> 3) & 1, k16 = rest >> 4;
        int g = lane >> 2, tig = lane & 3;
        int b = bgroup * 32 + nfrag * 8 + g;
        uint32_t regs[2];
#pragma unroll
        for (int kh = 0; kh < 2; kh++) {             // b0: k=2tig+{0,1}, b1: +8
            int k = k16 * 16 + 2 * tig + kh * 8;
            regs[kh] = pack_split(sa[b][k], sa[b][k + 1], split);
        }
        *(uint2*)(out + k16 * 4096 + bgroup * 2048 + split * 1024 + nfrag * 256 + lane * 8)
            = make_uint2(regs[0], regs[1]);
    }
}

// ---------------- HMMA LSTM layer ----------------
// grid = 128 (jt), 128 threads. Warp: jsub = w>>1 (16 j), bgroup = w&1 (32 b).
__global__ void __launch_bounds__(128, 1) lstm_mma_layer(
    const char* __restrict__ wimg, int nch,
    const char* b0p, int nq0, const char* b1p, int nq1, const char* b2p, int nq2,
    const float* __restrict__ bias,
    const float* __restrict__ hprev, const float* __restrict__ cprev,
    float* __restrict__ hout, float* __restrict__ cout,
    char* __restrict__ himg, float* __restrict__ outp, int t)
{
    __shared__ __align__(16) char sbuf[49152];       // 2 x [A 8KB | B 16KB]
    const int tid = threadIdx.x;
    const int lane = tid & 31, w = tid >> 5;
    const int jt = blockIdx.x;
    const int jsub = w >> 1, bgroup = w & 1;
    const uint32_t sb = smem_u32(sbuf);
    const char* achunks = wimg + (size_t)jt * nch * A_CH;

    float acc[4][4];
#pragma unroll
    for (int f = 0; f < 4; f++)
#pragma unroll
        for (int e = 0; e < 4; e++) acc[f][e] = 0.0f;

    auto bsrc = [&](int i) -> const char* {
        if (i < nq0) return b0p + (size_t)i * B_CH;
        i -= nq0;
        if (i < nq1) return b1p + (size_t)i * B_CH;
        i -= nq1;
        return b2p + (size_t)i * B_CH;
    };
    auto copy_chunk = [&](int ci, int sel) {
        const char* sA = achunks + (size_t)ci * A_CH + tid * 16;
        uint32_t dA = sb + sel * 24576 + tid * 16;
#pragma unroll
        for (int u = 0; u < 4; u++)
            asm volatile("cp.async.cg.shared.global [%0], [%1], 16;"
                         :: "r"(dA + u * 2048), "l"(sA + u * 2048));
        const char* sB = bsrc(ci) + tid * 16;
        uint32_t dB = sb + sel * 24576 + 8192 + tid * 16;
#pragma unroll
        for (int u = 0; u < 8; u++)
            asm volatile("cp.async.cg.shared.global [%0], [%1], 16;"
                         :: "r"(dB + u * 2048), "l"(sB + u * 2048));
        asm volatile("cp.async.commit_group;" ::: "memory");
    };

    copy_chunk(0, 0);
    for (int i = 0; i < nch; i++) {
        if (i + 1 < nch) {
            copy_chunk(i + 1, (i + 1) & 1);
            asm volatile("cp.async.wait_group 1;" ::: "memory");
        } else {
            asm volatile("cp.async.wait_group 0;" ::: "memory");
        }
        __syncthreads();

        const char* base = sbuf + (i & 1) * 24576;
        const char* Ab = base + jsub * 1024 + lane * 16;
        const char* Bb = base + 8192 + bgroup * 2048 + lane * 8;
#pragma unroll
        for (int k16 = 0; k16 < 4; k16++) {
            const uint4 ah = *(const uint4*)(Ab + k16 * 2048);
            const uint4 al = *(const uint4*)(Ab + k16 * 2048 + 512);
#pragma unroll
            for (int f = 0; f < 4; f++) {
                const uint2 bh = *(const uint2*)(Bb + k16 * 4096 + f * 256);
                const uint2 bl = *(const uint2*)(Bb + k16 * 4096 + 1024 + f * 256);
                MMA(acc[f], ah, bh);
                MMA(acc[f], ah, bl);
                MMA(acc[f], al, bh);
            }
        }
        __syncthreads();
    }

    // ---- epilogue ----
    float* zsm = (float*)sbuf;                       // [32 jloc][66] padded (8.4 KB, aliases buf0)
    const int g = lane >> 2, tig = lane & 3;
#pragma unroll
    for (int f = 0; f < 4; f++) {
        const int bc = bgroup * 32 + f * 8 + 2 * tig;
        zsm[(jsub * 16 + g) * 66 + bc]         = acc[f][0];
        zsm[(jsub * 16 + g) * 66 + bc + 1]     = acc[f][1];
        zsm[(jsub * 16 + g + 8) * 66 + bc]     = acc[f][2];
        zsm[(jsub * 16 + g + 8) * 66 + bc + 1] = acc[f][3];
    }
    __syncthreads();

    const int ni = tid >> 4;                         // 0..7
    const int bq = (tid & 15) * 4;                   // 0..60
    const int ng = jt * 8 + ni;
    const float bfv = bias[ng], biv = bias[HH + ng], bov = bias[2 * HH + ng], bgv = bias[3 * HH + ng];

    // h-image fragment position for (b, ng): k-dim = ng
    const int k16h = (ng >> 4) & 3, kk = ng & 15;
    const int tigh = (kk >> 1) & 3, ch = kk & 1, khalf = kk >> 3;
    char* chb = himg + (size_t)(ng >> 6) * B_CH + k16h * 4096;
    const int inoff = khalf * 4 + ch * 2;

#pragma unroll
    for (int jb = 0; jb < 4; jb++) {
        const int b = bq + jb;
        const float zf = zsm[(0 + ni) * 66 + b] + bfv;
        const float zi = zsm[(8 + ni) * 66 + b] + biv;
        const float zo = zsm[(16 + ni) * 66 + b] + bov;
        const float zg = zsm[(24 + ni) * 66 + b] + bgv;
        const int sidx = b * HH + ng;
        const float cold = cprev[sidx], hold = hprev[sidx];

        float c1 = sigf(zf) * cold + sigf(zi) * tanhf(zg);
        float h1 = sigf(zo) * tanhf(c1);
        if (!(t < g_len[b])) { c1 = cold; h1 = hold; }

        cout[sidx] = c1;
        hout[sidx] = h1;
        if (outp) outp[sidx] = h1;

        const int bloc = b & 31;
        char* p = chb + (b >> 5) * 2048 + (bloc >> 3) * 256 + ((bloc & 7) * 4 + tigh) * 8 + inoff;
        const uint16_t hb = bf16bits(h1);
        *(uint16_t*)p          = hb;                          // hi (split 0)
        *(uint16_t*)(p + 1024) = bf16bits(h1 - bf16val(hb));  // lo (split 1)
    }
}

// ---------------- host ----------------
extern "C" void kernel_launch(void* const* d_in, const int* in_sizes, int n_in,
                              void* d_out, int out_size) {
    const float* x    = (const float*)d_in[0];
    const void*  len  = d_in[1];
    const float* h0   = (const float*)d_in[2];
    const float* c0   = (const float*)d_in[3];
    const float* Wbh0 = (const float*)d_in[4];
    const float* Whh0 = (const float*)d_in[5];
    const float* Wth0 = (const float*)d_in[6];
    const float* b0   = (const float*)d_in[7];
    const float* Wbh1 = (const float*)d_in[8];
    const float* Whh1 = (const float*)d_in[9];
    const float* Wth1 = (const float*)d_in[10];
    const float* b1   = (const float*)d_in[11];
    const float* Wih2 = (const float*)d_in[12];
    const float* Whh2 = (const float*)d_in[13];
    const float* b2   = (const float*)d_in[14];

    float* out  = (float*)d_out;
    float* Hout = out + (size_t)TT * BB * HH;
    float* Cout = Hout + SBUF;

    void* p;
    cudaGetSymbolAddress(&p, g_h);    float* Hs   = (float*)p;
    cudaGetSymbolAddress(&p, g_c);    float* Cs   = (float*)p;
    cudaGetSymbolAddress(&p, g_wimg); char*  Wimg = (char*)p;
    cudaGetSymbolAddress(&p, g_ximg); char*  Ximg = (char*)p;
    cudaGetSymbolAddress(&p, g_himg); char*  Himg = (char*)p;

    const size_t HIMG_L = 16 * B_CH;
    auto himg_at = [&](int pp, int layer) { return Himg + ((size_t)pp * 3 + layer) * HIMG_L; };

    prep_len_kernel<<<1, 32>>>(len);
    init_state_kernel<<<(SBUF + 255) / 256, 256>>>(h0, c0);

    struct WJob { const float* W; unsigned long long base; int NCH; int so; int nq; };
    const WJob jobs[8] = {
        { Whh0, WIMG_L0, NCH0,  0, 16 }, { Wbh0, WIMG_L0, NCH0, 16,  8 }, { Wth0, WIMG_L0, NCH0, 24, 16 },
        { Whh1, WIMG_L1, NCH1,  0, 16 }, { Wbh1, WIMG_L1, NCH1, 16, 16 }, { Wth1, WIMG_L1, NCH1, 32, 16 },
        { Whh2, WIMG_L2, NCH2,  0, 16 }, { Wih2, WIMG_L2, NCH2, 16, 16 },
    };
    for (int j = 0; j < 8; j++) {
        dim3 g(jobs[j].nq, 128);
        prep_w_kernel<<<g, 128>>>(jobs[j].W, Wimg + jobs[j].base, jobs[j].NCH, jobs[j].so);
    }
    { dim3 g(8, TT); prep_act_kernel<<<g, 128>>>(x,  II, Ximg, 8); }           // x images
    { dim3 g(16, 3); prep_act_kernel<<<g, 128>>>(h0, HH, himg_at(0, 0), 16); } // initial h images

    for (int t = 0; t < TT; t++) {
        const int pv = t & 1, cu = pv ^ 1;
        float* hp = Hs + pv * SBUF; float* hc = Hs + cu * SBUF;
        float* cp = Cs + pv * SBUF; float* cc = Cs + cu * SBUF;
        char* xt = Ximg + (size_t)t * 8 * B_CH;

        // layer 0: z = h0_prev@Whh0 + x_t@Wbh0 + h1_prev@Wth0 + b0
        lstm_mma_layer<<<128, 128>>>(
            Wimg + WIMG_L0, NCH0,
            himg_at(pv, 0), 16, xt, 8, himg_at(pv, 1), 16,
            b0, hp + 0 * BB * HH, cp + 0 * BB * HH,
            hc + 0 * BB * HH, cc + 0 * BB * HH,
            himg_at(cu, 0), nullptr, t);

        // layer 1: z = h1_prev@Whh1 + h0_new@Wbh1 + h2_prev@Wth1 + b1
        lstm_mma_layer<<<128, 128>>>(
            Wimg + WIMG_L1, NCH1,
            himg_at(pv, 1), 16, himg_at(cu, 0), 16, himg_at(pv, 2), 16,
            b1, hp + 1 * BB * HH, cp + 1 * BB * HH,
            hc + 1 * BB * HH, cc + 1 * BB * HH,
            himg_at(cu, 1), nullptr, t);

        // layer 2: z = h2_prev@Whh2 + h1_new@Wih2 + b2 ; writes output[t]
        lstm_mma_layer<<<128, 128>>>(
            Wimg + WIMG_L2, NCH2,
            himg_at(pv, 2), 16, himg_at(cu, 1), 16, nullptr, 0,
            b2, hp + 2 * BB * HH, cp + 2 * BB * HH,
            hc + 2 * BB * HH, cc + 2 * BB * HH,
            himg_at(cu, 2), out + (size_t)t * BB * HH, t);
    }

    finalize_kernel<<<(SBUF + 255) / 256, 256>>>(Hout, Cout);
}

// round 7
// speedup vs baseline: 4.8590x; 1.1017x over previous
#include <cuda_runtime.h>
#include <cuda_bf16.h>
#include <cstdint>

#define TT   256
#define BB   64
#define II   512
#define HH   1024
#define SBUF (3 * BB * HH)

#define A_CH 8192      // weight chunk: 32j x 64k x (hi+lo) bf16, fragment order
#define B_CH 16384     // activation chunk: 64b x 64k x (hi+lo) bf16, fragment order
#define NCH0 40        // layer0: h(16) + x(8) + h(16)
#define NCH1 48
#define NCH2 32

#define WIMG_L0 0ULL
#define WIMG_L1 (WIMG_L0 + 128ULL * NCH0 * A_CH)
#define WIMG_L2 (WIMG_L1 + 128ULL * NCH1 * A_CH)
#define WIMG_TOT (WIMG_L2 + 128ULL * NCH2 * A_CH)

#define STG_BYTES 24576        // A 8KB + B 16KB per stage
#define NSTG 4
#define SMEM_DYN (NSTG * STG_BYTES)   // 98304

__device__ __align__(16) char g_wimg[WIMG_TOT];
__device__ __align__(16) char g_ximg[(size_t)TT * 8 * B_CH];
__device__ __align__(16) char g_himg[2][3][16 * B_CH];
__device__ float g_h[2 * SBUF];
__device__ float g_c[2 * SBUF];
__device__ int   g_len[BB];

__device__ __forceinline__ uint32_t smem_u32(const void* p) {
    uint32_t a;
    asm("{ .reg .u64 t; cvta.to.shared.u64 t, %1; cvt.u32.u64 %0, t; }" : "=r"(a) : "l"(p));
    return a;
}
__device__ __forceinline__ float sigf(float x) { return 1.0f / (1.0f + __expf(-x)); }
__device__ __forceinline__ uint16_t bf16bits(float v) {
    __nv_bfloat16 b = __float2bfloat16(v);
    return *(uint16_t*)&b;
}
__device__ __forceinline__ float bf16val(uint16_t u) {
    __nv_bfloat16 b = *(__nv_bfloat16*)&u;
    return __bfloat162float(b);
}
__device__ __forceinline__ uint32_t pack_split(float v0, float v1, int split) {
    uint16_t h0 = bf16bits(v0), h1 = bf16bits(v1);
    if (split == 0) return (uint32_t)h0 | ((uint32_t)h1 << 16);
    uint16_t l0 = bf16bits(v0 - bf16val(h0)), l1 = bf16bits(v1 - bf16val(h1));
    return (uint32_t)l0 | ((uint32_t)l1 << 16);
}

#define MMA(c, a, b) \
    asm volatile("mma.sync.aligned.m16n8k16.row.col.f32.bf16.bf16.f32 " \
        "{%0,%1,%2,%3}, {%4,%5,%6,%7}, {%8,%9}, {%0,%1,%2,%3};" \
        : "+f"((c)[0]), "+f"((c)[1]), "+f"((c)[2]), "+f"((c)[3]) \
        : "r"((a).x), "r"((a).y), "r"((a).z), "r"((a).w), "r"((b).x), "r"((b).y))

// ---------------- prep kernels ----------------
__global__ void prep_len_kernel(const void* lenbuf) {
    if (threadIdx.x == 0 && blockIdx.x == 0) {
        const long long* L64 = (const long long*)lenbuf;
        const int*       L32 = (const int*)lenbuf;
        bool is64 = true;
        for (int b = 0; b < 32; b++) {
            long long v = L64[b];
            if (v < 0 || v > TT) { is64 = false; break; }
        }
        for (int b = 0; b < BB; b++) g_len[b] = is64 ? (int)L64[b] : L32[b];
    }
}
__global__ void init_state_kernel(const float* __restrict__ h0, const float* __restrict__ c0) {
    int i = blockIdx.x * blockDim.x + threadIdx.x;
    if (i < SBUF) { g_h[i] = h0[i]; g_c[i] = c0[i]; }
}
__global__ void finalize_kernel(float* __restrict__ Hout, float* __restrict__ Cout) {
    int i = blockIdx.x * blockDim.x + threadIdx.x;
    if (i < SBUF) { Hout[i] = g_h[i]; Cout[i] = g_c[i]; }   // t=255 odd -> cur in buf 0
}

// All 8 weight-prep jobs in ONE launch (grid.z = job) so the layer kernel is launch #6 for ncu.
struct WJobs {
    const float* W[8];
    unsigned long long off[8];
    int NCH[8];
    int so[8];
    int nq[8];
};
__global__ void __launch_bounds__(128) prep_w_all(WJobs jb, char* __restrict__ wimg) {
    __shared__ float sw[64][36];
    const int jidx = blockIdx.z;
    const int q = blockIdx.x, jt = blockIdx.y, tid = threadIdx.x;
    if (q >= jb.nq[jidx]) return;
    const float* __restrict__ W = jb.W[jidx];
    char* out = wimg + jb.off[jidx] + ((size_t)jt * jb.NCH[jidx] + jb.so[jidx] + q) * A_CH;
    const int kb = q * 64;

#pragma unroll
    for (int r = 0; r < 4; r++) {
        int u = tid + 128 * r;
        int k = u >> 3, rem = u & 7, gate = rem >> 1, pair = rem & 1;
        const float4 v = *(const float4*)(W + (size_t)(kb + k) * 4096 + gate * 1024 + jt * 8 + pair * 4);
        float* d = &sw[k][gate * 8 + pair * 4];
        d[0] = v.x; d[1] = v.y; d[2] = v.z; d[3] = v.w;
    }
    __syncthreads();
#pragma unroll
    for (int r = 0; r < 4; r++) {
        int u = tid + 128 * r;
        int lane = u & 31, rest = u >> 5;
        int split = rest & 1, jsub = (rest >> 1) & 1, k16 = rest >> 2;
        int g = lane >> 2, tig = lane & 3;
        uint32_t regs[4];
#pragma unroll
        for (int rg = 0; rg < 4; rg++) {
            int col = jsub * 16 + (rg & 1) * 8 + g;
            int kx  = k16 * 16 + 2 * tig + (rg >> 1) * 8;
            regs[rg] = pack_split(sw[kx][col], sw[kx + 1][col], split);
        }
        *(uint4*)(out + k16 * 2048 + jsub * 1024 + split * 512 + lane * 16)
            = make_uint4(regs[0], regs[1], regs[2], regs[3]);
    }
}

__global__ void __launch_bounds__(128) prep_act_kernel(
    const float* __restrict__ src, int rowlen, char* __restrict__ outbase, int ch_per_outer)
{
    __shared__ float sa[64][68];
    const int q = blockIdx.x, o = blockIdx.y, tid = threadIdx.x;
    const int kb = q * 64;
    char* out = outbase + ((size_t)o * ch_per_outer + q) * B_CH;

#pragma unroll
    for (int r = 0; r < 8; r++) {
        int u = tid + 128 * r;
        int b = u >> 4, c4 = u & 15;
        const float4 v = *(const float4*)(src + ((size_t)o * BB + b) * rowlen + kb + c4 * 4);
        float* d = &sa[b][c4 * 4];
        d[0] = v.x; d[1] = v.y; d[2] = v.z; d[3] = v.w;
    }
    __syncthreads();
#pragma unroll
    for (int r = 0; r < 16; r++) {
        int u = tid + 128 * r;
        int lane = u & 31, rest = u >> 5;
        int nfrag = rest & 3, split = (rest >> 2) & 1, bgroup = (rest >> 3) & 1, k16 = rest >> 4;
        int g = lane >> 2, tig = lane & 3;
        int b = bgroup * 32 + nfrag * 8 + g;
        uint32_t regs[2];
#pragma unroll
        for (int kh = 0; kh < 2; kh++) {
            int k = k16 * 16 + 2 * tig + kh * 8;
            regs[kh] = pack_split(sa[b][k], sa[b][k + 1], split);
        }
        *(uint2*)(out + k16 * 4096 + bgroup * 2048 + split * 1024 + nfrag * 256 + lane * 8)
            = make_uint2(regs[0], regs[1]);
    }
}

// ---------------- HMMA LSTM layer ----------------
// grid = 128 jt, 256 threads (8 warps). Warp: jsub = w>>2 (16 j), bg16 = w&3 (16 b).
// 4-stage cp.async pipeline, ONE __syncthreads per chunk.
__global__ void __launch_bounds__(256, 1) lstm_mma_layer(
    const char* __restrict__ wimg, int nch,
    const char* b0p, int nq0, const char* b1p, int nq1, const char* b2p, int nq2,
    const float* __restrict__ bias,
    const float* __restrict__ hprev, const float* __restrict__ cprev,
    float* __restrict__ hout, float* __restrict__ cout,
    char* __restrict__ himg, float* __restrict__ outp, int t)
{
    extern __shared__ __align__(16) char sbuf[];   // NSTG x [A 8KB | B 16KB]
    const int tid = threadIdx.x;
    const int lane = tid & 31, w = tid >> 5;
    const int jt = blockIdx.x;
    const int jsub = w >> 2, bg16 = w & 3;
    const uint32_t sb = smem_u32(sbuf);
    const char* achunks = wimg + (size_t)jt * nch * A_CH;

    float acc[2][4];
#pragma unroll
    for (int f = 0; f < 2; f++)
#pragma unroll
        for (int e = 0; e < 4; e++) acc[f][e] = 0.0f;

    auto bsrc = [&](int i) -> const char* {
        if (i < nq0) return b0p + (size_t)i * B_CH;
        i -= nq0;
        if (i < nq1) return b1p + (size_t)i * B_CH;
        i -= nq1;
        return b2p + (size_t)i * B_CH;
    };
    auto copy_chunk = [&](int ci) {
        const int stg = ci & 3;
        const char* sA = achunks + (size_t)ci * A_CH + tid * 16;
        uint32_t dA = sb + stg * STG_BYTES + tid * 16;
#pragma unroll
        for (int u = 0; u < 2; u++)
            asm volatile("cp.async.cg.shared.global [%0], [%1], 16;"
                         :: "r"(dA + u * 4096), "l"(sA + u * 4096));
        const char* sB = bsrc(ci) + tid * 16;
        uint32_t dB = sb + stg * STG_BYTES + 8192 + tid * 16;
#pragma unroll
        for (int u = 0; u < 4; u++)
            asm volatile("cp.async.cg.shared.global [%0], [%1], 16;"
                         :: "r"(dB + u * 4096), "l"(sB + u * 4096));
        asm volatile("cp.async.commit_group;" ::: "memory");
    };

    const int npre = (nch < NSTG - 1) ? nch : (NSTG - 1);
    for (int s = 0; s < npre; s++) copy_chunk(s);

    for (int i = 0; i < nch; i++) {
        const int rem = nch - 1 - i;
        if (rem >= 2)      asm volatile("cp.async.wait_group 2;" ::: "memory");
        else if (rem == 1) asm volatile("cp.async.wait_group 1;" ::: "memory");
        else               asm volatile("cp.async.wait_group 0;" ::: "memory");
        __syncthreads();                       // chunk i visible; MMA(i-1) done by all warps

        if (i + NSTG - 1 < nch) copy_chunk(i + NSTG - 1);   // buffer (i-1)&3: provably free

        const char* base = sbuf + (i & 3) * STG_BYTES;
        const char* Ab = base + jsub * 1024 + lane * 16;
        const char* Bb = base + 8192 + (bg16 >> 1) * 2048 + lane * 8;
#pragma unroll
        for (int k16 = 0; k16 < 4; k16++) {
            const uint4 ah = *(const uint4*)(Ab + k16 * 2048);
            const uint4 al = *(const uint4*)(Ab + k16 * 2048 + 512);
#pragma unroll
            for (int f = 0; f < 2; f++) {
                const int nf = (bg16 & 1) * 2 + f;
                const uint2 bh = *(const uint2*)(Bb + k16 * 4096 + nf * 256);
                const uint2 bl = *(const uint2*)(Bb + k16 * 4096 + 1024 + nf * 256);
                MMA(acc[f], ah, bh);
                MMA(acc[f], ah, bl);
                MMA(acc[f], al, bh);
            }
        }
    }
    __syncthreads();                           // all MMAs done before smem reuse

    // ---- epilogue ----
    float* zsm = (float*)sbuf;                 // [32 jloc][66] padded
    const int g = lane >> 2, tig = lane & 3;
#pragma unroll
    for (int f = 0; f < 2; f++) {
        const int bc = bg16 * 16 + f * 8 + 2 * tig;
        zsm[(jsub * 16 + g) * 66 + bc]         = acc[f][0];
        zsm[(jsub * 16 + g) * 66 + bc + 1]     = acc[f][1];
        zsm[(jsub * 16 + g + 8) * 66 + bc]     = acc[f][2];
        zsm[(jsub * 16 + g + 8) * 66 + bc + 1] = acc[f][3];
    }
    __syncthreads();

    const int ni = tid >> 5;                   // 0..7
    const int bq = (tid & 31) * 2;             // 0..62
    const int ng = jt * 8 + ni;
    const float bfv = bias[ng], biv = bias[HH + ng], bov = bias[2 * HH + ng], bgv = bias[3 * HH + ng];

    const int k16h = (ng >> 4) & 3, kk = ng & 15;
    const int tigh = (kk >> 1) & 3, ch = kk & 1, khalf = kk >> 3;
    char* chb = himg + (size_t)(ng >> 6) * B_CH + k16h * 4096;
    const int inoff = khalf * 4 + ch * 2;

#pragma unroll
    for (int jb = 0; jb < 2; jb++) {
        const int b = bq + jb;
        const float zf = zsm[(0 + ni) * 66 + b] + bfv;
        const float zi = zsm[(8 + ni) * 66 + b] + biv;
        const float zo = zsm[(16 + ni) * 66 + b] + bov;
        const float zg = zsm[(24 + ni) * 66 + b] + bgv;
        const int sidx = b * HH + ng;
        const float cold = cprev[sidx], hold = hprev[sidx];

        float c1 = sigf(zf) * cold + sigf(zi) * tanhf(zg);
        float h1 = sigf(zo) * tanhf(c1);
        if (!(t < g_len[b])) { c1 = cold; h1 = hold; }

        cout[sidx] = c1;
        hout[sidx] = h1;
        if (outp) outp[sidx] = h1;

        const int bloc = b & 31;
        char* p = chb + (b >> 5) * 2048 + (bloc >> 3) * 256 + ((bloc & 7) * 4 + tigh) * 8 + inoff;
        const uint16_t hb = bf16bits(h1);
        *(uint16_t*)p          = hb;
        *(uint16_t*)(p + 1024) = bf16bits(h1 - bf16val(hb));
    }
}

// ---------------- host ----------------
extern "C" void kernel_launch(void* const* d_in, const int* in_sizes, int n_in,
                              void* d_out, int out_size) {
    const float* x    = (const float*)d_in[0];
    const void*  len  = d_in[1];
    const float* h0   = (const float*)d_in[2];
    const float* c0   = (const float*)d_in[3];
    const float* Wbh0 = (const float*)d_in[4];
    const float* Whh0 = (const float*)d_in[5];
    const float* Wth0 = (const float*)d_in[6];
    const float* b0   = (const float*)d_in[7];
    const float* Wbh1 = (const float*)d_in[8];
    const float* Whh1 = (const float*)d_in[9];
    const float* Wth1 = (const float*)d_in[10];
    const float* b1   = (const float*)d_in[11];
    const float* Wih2 = (const float*)d_in[12];
    const float* Whh2 = (const float*)d_in[13];
    const float* b2   = (const float*)d_in[14];

    float* out  = (float*)d_out;
    float* Hout = out + (size_t)TT * BB * HH;
    float* Cout = Hout + SBUF;

    void* p;
    cudaGetSymbolAddress(&p, g_h);    float* Hs   = (float*)p;
    cudaGetSymbolAddress(&p, g_c);    float* Cs   = (float*)p;
    cudaGetSymbolAddress(&p, g_wimg); char*  Wimg = (char*)p;
    cudaGetSymbolAddress(&p, g_ximg); char*  Ximg = (char*)p;
    cudaGetSymbolAddress(&p, g_himg); char*  Himg = (char*)p;

    const size_t HIMG_L = 16 * B_CH;
    auto himg_at = [&](int pp, int layer) { return Himg + ((size_t)pp * 3 + layer) * HIMG_L; };

    cudaFuncSetAttribute(lstm_mma_layer, cudaFuncAttributeMaxDynamicSharedMemorySize, SMEM_DYN);

    // Launches 1-5 (so launch #6 = first lstm_mma_layer, which ncu captures):
    prep_len_kernel<<<1, 32>>>(len);
    init_state_kernel<<<(SBUF + 255) / 256, 256>>>(h0, c0);

    WJobs jb;
    jb.W[0] = Whh0; jb.off[0] = WIMG_L0; jb.NCH[0] = NCH0; jb.so[0] = 0;  jb.nq[0] = 16;
    jb.W[1] = Wbh0; jb.off[1] = WIMG_L0; jb.NCH[1] = NCH0; jb.so[1] = 16; jb.nq[1] = 8;
    jb.W[2] = Wth0; jb.off[2] = WIMG_L0; jb.NCH[2] = NCH0; jb.so[2] = 24; jb.nq[2] = 16;
    jb.W[3] = Whh1; jb.off[3] = WIMG_L1; jb.NCH[3] = NCH1; jb.so[3] = 0;  jb.nq[3] = 16;
    jb.W[4] = Wbh1; jb.off[4] = WIMG_L1; jb.NCH[4] = NCH1; jb.so[4] = 16; jb.nq[4] = 16;
    jb.W[5] = Wth1; jb.off[5] = WIMG_L1; jb.NCH[5] = NCH1; jb.so[5] = 32; jb.nq[5] = 16;
    jb.W[6] = Whh2; jb.off[6] = WIMG_L2; jb.NCH[6] = NCH2; jb.so[6] = 0;  jb.nq[6] = 16;
    jb.W[7] = Wih2; jb.off[7] = WIMG_L2; jb.NCH[7] = NCH2; jb.so[7] = 16; jb.nq[7] = 16;
    {
        dim3 g(16, 128, 8);
        prep_w_all<<<g, 128>>>(jb, Wimg);
    }
    { dim3 g(8, TT); prep_act_kernel<<<g, 128>>>(x,  II, Ximg, 8); }
    { dim3 g(16, 3); prep_act_kernel<<<g, 128>>>(h0, HH, himg_at(0, 0), 16); }

    for (int t = 0; t < TT; t++) {
        const int pv = t & 1, cu = pv ^ 1;
        float* hp = Hs + pv * SBUF; float* hc = Hs + cu * SBUF;
        float* cp = Cs + pv * SBUF; float* cc = Cs + cu * SBUF;
        char* xt = Ximg + (size_t)t * 8 * B_CH;

        lstm_mma_layer<<<128, 256, SMEM_DYN>>>(
            Wimg + WIMG_L0, NCH0,
            himg_at(pv, 0), 16, xt, 8, himg_at(pv, 1), 16,
            b0, hp + 0 * BB * HH, cp + 0 * BB * HH,
            hc + 0 * BB * HH, cc + 0 * BB * HH,
            himg_at(cu, 0), nullptr, t);

        lstm_mma_layer<<<128, 256, SMEM_DYN>>>(
            Wimg + WIMG_L1, NCH1,
            himg_at(pv, 1), 16, himg_at(cu, 0), 16, himg_at(pv, 2), 16,
            b1, hp + 1 * BB * HH, cp + 1 * BB * HH,
            hc + 1 * BB * HH, cc + 1 * BB * HH,
            himg_at(cu, 1), nullptr, t);

        lstm_mma_layer<<<128, 256, SMEM_DYN>>>(
            Wimg + WIMG_L2, NCH2,
            himg_at(pv, 2), 16, himg_at(cu, 1), 16, nullptr, 0,
            b2, hp + 2 * BB * HH, cp + 2 * BB * HH,
            hc + 2 * BB * HH, cc + 2 * BB * HH,
            himg_at(cu, 2), out + (size_t)t * BB * HH, t);
    }

    finalize_kernel<<<(SBUF + 255) / 256, 256>>>(Hout, Cout);
}